// round 16
// baseline (speedup 1.0000x reference)
#include <cuda_runtime.h>
#include <cuda_bf16.h>
#include <math.h>

#define NB 16  // batch

// ---------------- packed f32x2 helpers (sm_100+ PTX) --------------------------
#define FMA2(d, a, b, c) \
    asm("fma.rn.f32x2 %0, %1, %2, %3;" : "=l"(d) : "l"(a), "l"(b), "l"(c))
__device__ __forceinline__ unsigned long long pack2(float lo, float hi) {
    unsigned long long r;
    asm("mov.b64 %0, {%1, %2};" : "=l"(r) : "r"(__float_as_uint(lo)), "r"(__float_as_uint(hi)));
    return r;
}
__device__ __forceinline__ void unpack2(unsigned long long v, float& lo, float& hi) {
    unsigned int a, b;
    asm("mov.b64 {%0, %1}, %2;" : "=r"(a), "=r"(b) : "l"(v));
    lo = __uint_as_float(a); hi = __uint_as_float(b);
}

// ---------------- scratch (device globals; no allocation allowed) -------------
__device__ float g_v[NB*49*2048];        // transposed vision (B,49,2048)
__device__ float g_tv[NB*49*49];         // vision hidden (raw linear out)
__device__ float g_vquery[NB*49*2048];
__device__ float g_vkeys[NB*49*2048];    // raw conv out (BN folded at consumer)
__device__ float g_scores[(size_t)NB*2048*2048];  // 268 MB raw (scaled) logits
__device__ float g_ta[NB*64*64];
__device__ float g_aquery[NB*64*128];
__device__ float g_akeys[NB*64*128];
__device__ float g_scores_a[NB*128*128];
__device__ float g_bnscale[4*64];        // fused BN: x*scale + shift
__device__ float g_bnshift[4*64];
__device__ float g_pmax[(size_t)NB*2048*32];
__device__ float g_psum[(size_t)NB*2048*32];
__device__ float g_smax[NB*2048];
__device__ float g_sinv[NB*2048];
__device__ float g_vpart[4*NB*49*2048];  // k_vout partials (25.7 MB)

// ---------------- transpose Vision (B,2048,49) -> g_v (B,49,2048) -------------
__global__ void k_transpose(const float* __restrict__ vis, float* __restrict__ out) {
    int b = blockIdx.x, dt = blockIdx.y;
    __shared__ float s[32*49];
    int d0 = dt * 32;
    const float* src = vis + ((size_t)b*2048 + d0)*49;
    for (int i = threadIdx.x; i < 32*49; i += blockDim.x) s[i] = src[i];
    __syncthreads();
    float* dst = out + (size_t)b*49*2048;
    for (int i = threadIdx.x; i < 49*32; i += blockDim.x) {
        int n = i >> 5, dd = i & 31;
        dst[n*2048 + d0 + dd] = s[dd*49 + n];
    }
}

// ---- out[bn][h] = bias[h] + sum_d x[bn][d]*W[h][d]  (ROWS rows per block) ----
template<int D, int H, int ROWS>
__global__ void __launch_bounds__(256) k_rowAT(const float* __restrict__ x,
                                               const float* __restrict__ W,
                                               const float* __restrict__ bias,
                                               float* __restrict__ out) {
    int bn0 = blockIdx.x*ROWS;
    __shared__ float s[ROWS*D];
    const float* rowp = x + (size_t)bn0*D;
    for (int i = threadIdx.x*4; i < ROWS*D; i += 1024)
        *(float4*)&s[i] = *(const float4*)&rowp[i];
    __syncthreads();
    int warp = threadIdx.x >> 5, lane = threadIdx.x & 31;
    for (int idx = warp; idx < ROWS*H; idx += 8) {
        int r = idx / H, h = idx - r*H;
        const float* w = W + (size_t)h*D;
        const float* sr = s + r*D;
        float acc = 0.f;
        #pragma unroll
        for (int d = lane*4; d < D; d += 128) {
            float4 wv = *(const float4*)&w[d];
            float4 sv = *(const float4*)&sr[d];
            acc += sv.x*wv.x + sv.y*wv.y + sv.z*wv.z + sv.w*wv.w;
        }
        #pragma unroll
        for (int off = 16; off > 0; off >>= 1)
            acc += __shfl_xor_sync(0xffffffffu, acc, off);
        if (lane == 0) out[(size_t)(bn0+r)*H + h] = acc + bias[h];
    }
}

// ---- tiled: out[bn][d] = bias[d] + sum_h relu(BN(act[bn][h])) * W[d][h] ------
// W is (D, H) row-major (untransposed). BNT bn-rows x 128 d per block.
template<int H, int D, int NTOK, int BNT>
__global__ void __launch_bounds__(128) k_rowBt(const float* __restrict__ act,
                                               const float* __restrict__ W,
                                               const float* __restrict__ bias,
                                               const float* __restrict__ scl,
                                               const float* __restrict__ sft,
                                               float* __restrict__ out) {
    constexpr int WS = (H % 32 == 0) ? H + 1 : H;   // padded row stride
    int d0 = blockIdx.x*128, bn0 = blockIdx.y*BNT;
    __shared__ float as2[H*BNT];      // [h][r]
    __shared__ float wsm[128*WS];     // [dd][h]
    for (int i = threadIdx.x; i < BNT*H; i += 128) {
        int r = i / H, h = i - r*H;
        int n = (bn0 + r) % NTOK;
        as2[h*BNT + r] = fmaxf(fmaf(act[(size_t)(bn0+r)*H + h], scl[n], sft[n]), 0.f);
    }
    const float* wsrc = W + (size_t)d0*H;
    for (int i = threadIdx.x; i < 128*H; i += 128) {
        int dd = i / H, h = i - dd*H;
        wsm[dd*WS + h] = wsrc[i];
    }
    __syncthreads();
    int d = d0 + threadIdx.x;
    unsigned long long acc2[BNT/2];
    #pragma unroll
    for (int k = 0; k < BNT/2; k++) acc2[k] = 0ULL;
    const float* wrow = &wsm[threadIdx.x*WS];
    #pragma unroll
    for (int h = 0; h < H; h++) {
        float wv = wrow[h];
        unsigned long long wd = pack2(wv, wv);
        const unsigned long long* ap = (const unsigned long long*)&as2[h*BNT];
        #pragma unroll
        for (int k = 0; k < BNT/2; k++) FMA2(acc2[k], wd, ap[k], acc2[k]);
    }
    float bv = bias[d];
    #pragma unroll
    for (int k = 0; k < BNT/2; k++) {
        float lo, hi;
        unpack2(acc2[k], lo, hi);
        out[(size_t)(bn0 + 2*k)*D + d] = lo + bv;
        out[(size_t)(bn0 + 2*k + 1)*D + d] = hi + bv;
    }
}

// ---- audio 1x1 conv: out[b][o][d] = bias[o] + sum_n W[o][n]*x[b][n][d] -------
template<int N, int D>
__global__ void k_conv(const float* __restrict__ x, const float* __restrict__ W,
                       const float* __restrict__ bias, float* __restrict__ out, int O) {
    int b = blockIdx.y, o = blockIdx.x;
    __shared__ float w[N];
    for (int i = threadIdx.x; i < N; i += blockDim.x) w[i] = W[o*N + i];
    __syncthreads();
    const float* xb = x + (size_t)b*N*D;
    float bo = bias[o];
    for (int d = threadIdx.x; d < D; d += blockDim.x) {
        float acc = bo;
        #pragma unroll
        for (int n = 0; n < N; n++) acc += w[n]*xb[n*D + d];
        out[((size_t)b*O + o)*D + d] = acc;
    }
}

// ---- vision 1x1 conv as smem mini-GEMM (f32x2, 49 accumulators) --------------
__global__ void __launch_bounds__(128) k_convv(const float* __restrict__ x,
                                               const float* __restrict__ W,
                                               const float* __restrict__ bias,
                                               float* __restrict__ out) {
    int b = blockIdx.y, d0 = blockIdx.x*128;
    __shared__ float xs[49*128];
    __shared__ float wst[49*50];   // wst[n][o], o padded to 50 (o=49 -> 0)
    __shared__ float bs[50];
    const float* xb = x + (size_t)b*49*2048;
    for (int i = threadIdx.x; i < 49*32; i += 128) {
        int n = i >> 5, dd4 = (i & 31) << 2;
        *(float4*)&xs[n*128 + dd4] = *(const float4*)&xb[n*2048 + d0 + dd4];
    }
    for (int i = threadIdx.x; i < 49*50; i += 128) {
        int n = i / 50, o = i - n*50;
        wst[i] = (o < 49) ? W[o*49 + n] : 0.f;
    }
    if (threadIdx.x < 50) bs[threadIdx.x] = (threadIdx.x < 49) ? bias[threadIdx.x] : 0.f;
    __syncthreads();
    int dd = threadIdx.x;
    unsigned long long acc2[25];
    #pragma unroll
    for (int k = 0; k < 25; k++) acc2[k] = 0ULL;
    #pragma unroll 7
    for (int n = 0; n < 49; n++) {
        float xv = xs[n*128 + dd];
        unsigned long long xd = pack2(xv, xv);
        const unsigned long long* wr = (const unsigned long long*)&wst[n*50];
        #pragma unroll
        for (int k = 0; k < 25; k++) FMA2(acc2[k], xd, wr[k], acc2[k]);
    }
    #pragma unroll
    for (int k = 0; k < 25; k++) {
        float lo, hi;
        unpack2(acc2[k], lo, hi);
        int o = 2*k;
        out[((size_t)b*49 + o)*2048 + d0 + dd] = lo + bs[o];
        if (o + 1 < 49)
            out[((size_t)b*49 + o + 1)*2048 + d0 + dd] = hi + bs[o+1];
    }
}

// ---- 4 BN-stats in one launch: y = x*scale + shift ---------------------------
struct BNCfg { const float *x, *g, *bet; float *scl, *sft; int C, L, blk0; };

__global__ void k_bnstats4(BNCfg c0, BNCfg c1, BNCfg c2, BNCfg c3) {
    BNCfg cf = (blockIdx.x >= c3.blk0) ? c3 :
               (blockIdx.x >= c2.blk0) ? c2 :
               (blockIdx.x >= c1.blk0) ? c1 : c0;
    int c = blockIdx.x - cf.blk0;
    int C = cf.C, L = cf.L;
    float s = 0.f, s2 = 0.f;
    int nTot = NB * L;
    for (int i = threadIdx.x; i < nTot; i += blockDim.x) {
        int b = i / L, l = i - b*L;
        float v = cf.x[((size_t)b*C + c)*L + l];
        s += v; s2 += v*v;
    }
    __shared__ float rs[256], rs2[256];
    rs[threadIdx.x] = s; rs2[threadIdx.x] = s2;
    __syncthreads();
    for (int off = 128; off > 0; off >>= 1) {
        if ((int)threadIdx.x < off) { rs[threadIdx.x] += rs[threadIdx.x+off];
                                      rs2[threadIdx.x] += rs2[threadIdx.x+off]; }
        __syncthreads();
    }
    if (threadIdx.x == 0) {
        float m = rs[0] / nTot;
        float var = rs2[0] / nTot - m*m;
        float rstd = rsqrtf(var + 1e-5f);
        float a = rstd * cf.g[c];
        cf.scl[c] = a;
        cf.sft[c] = cf.bet[c] - m*a;
    }
}

// ---- audio scores: BN(keys) + logits + softmax fused -------------------------
__global__ void k_scores_a(const float* __restrict__ keys, const float* __restrict__ qry,
                           const float* __restrict__ scl, const float* __restrict__ sft,
                           float* __restrict__ sc) {
    int b = blockIdx.y, d = blockIdx.x;
    int e = threadIdx.x;                      // 128 threads
    __shared__ float kcol[64];
    if (e < 64)
        kcol[e] = fmaxf(fmaf(keys[((size_t)b*64 + e)*128 + d], scl[e], sft[e]), 0.f);
    __syncthreads();
    float acc = 0.f;
    const float* qb = qry + (size_t)b*64*128;
    #pragma unroll
    for (int n = 0; n < 64; n++) acc += kcol[n]*qb[n*128 + e];
    acc *= 0.08838834764831845f;              // 1/sqrt(128)
    __shared__ float red[128];
    red[e] = acc; __syncthreads();
    for (int off = 64; off > 0; off >>= 1) {
        if (e < off) red[e] = fmaxf(red[e], red[e+off]);
        __syncthreads();
    }
    float mx = red[0]; __syncthreads();
    float ex = __expf(acc - mx);
    red[e] = ex; __syncthreads();
    for (int off = 64; off > 0; off >>= 1) {
        if (e < off) red[e] += red[e+off];
        __syncthreads();
    }
    sc[((size_t)b*128 + d)*128 + e] = ex / red[0];
}

// ---- a_out[b][n][e] = sum_d a[b][n][d] * sc[b][d][e] -------------------------
__global__ void k_aout(const float* __restrict__ a, const float* __restrict__ sc,
                       float* __restrict__ out) {
    int b = blockIdx.y, n = blockIdx.x;
    int e = threadIdx.x;                      // 128
    __shared__ float ar[128];
    ar[e] = a[((size_t)b*64 + n)*128 + e];
    __syncthreads();
    float acc = 0.f;
    const float* sb = sc + (size_t)b*128*128;
    #pragma unroll 8
    for (int d = 0; d < 128; d++) acc += ar[d]*sb[d*128 + e];
    out[((size_t)b*64 + n)*128 + e] = acc;
}

// ---- vision logits (BN folded on keys, A pre-duplicated in smem) -------------
__global__ void __launch_bounds__(256) k_logits_v(const float* __restrict__ keys,
                                                  const float* __restrict__ qry,
                                                  const float* __restrict__ scl,
                                                  const float* __restrict__ sft,
                                                  float* __restrict__ sc,
                                                  float* __restrict__ pmax,
                                                  float* __restrict__ psum) {
    int b = blockIdx.z;
    int d0 = blockIdx.y * 64, e0 = blockIdx.x * 64;
    __shared__ float Asd[49][128];   // duplicated pairs: [n][2j], [n][2j+1] = key value j
    __shared__ float Bs[49][64];
    const float* kb = keys + (size_t)b*49*2048;
    const float* qb = qry  + (size_t)b*49*2048;
    for (int i = threadIdx.x; i < 49*16; i += 256) {
        int n = i >> 4, c = (i & 15) << 2;
        float a = __ldg(&scl[n]), s = __ldg(&sft[n]);
        float4 t = *(const float4*)&kb[n*2048 + d0 + c];
        t.x = fmaxf(fmaf(t.x, a, s), 0.f);
        t.y = fmaxf(fmaf(t.y, a, s), 0.f);
        t.z = fmaxf(fmaf(t.z, a, s), 0.f);
        t.w = fmaxf(fmaf(t.w, a, s), 0.f);
        float2* dst = (float2*)&Asd[n][c*2];
        dst[0] = make_float2(t.x, t.x);
        dst[1] = make_float2(t.y, t.y);
        dst[2] = make_float2(t.z, t.z);
        dst[3] = make_float2(t.w, t.w);
        *(float4*)&Bs[n][c] = *(const float4*)&qb[n*2048 + e0 + c];
    }
    __syncthreads();
    int tx = threadIdx.x & 15, ty = threadIdx.x >> 4;
    unsigned long long acc2[4][2];
    #pragma unroll
    for (int i = 0; i < 4; i++) { acc2[i][0] = 0ULL; acc2[i][1] = 0ULL; }
    #pragma unroll 7
    for (int n = 0; n < 49; n++) {
        ulonglong2 bq = *(const ulonglong2*)&Bs[n][tx*4];     // (b0,b1),(b2,b3)
        const unsigned long long* ap = (const unsigned long long*)&Asd[n][0];
        #pragma unroll
        for (int i = 0; i < 4; i++) {
            unsigned long long ad = ap[ty*4 + i];              // (a,a) ready pair
            FMA2(acc2[i][0], ad, bq.x, acc2[i][0]);
            FMA2(acc2[i][1], ad, bq.y, acc2[i][1]);
        }
    }
    const float scale = 0.02209708691207961f; // 1/sqrt(2048)
    float acc[4][4];
    #pragma unroll
    for (int i = 0; i < 4; i++) {
        unpack2(acc2[i][0], acc[i][0], acc[i][1]);
        unpack2(acc2[i][1], acc[i][2], acc[i][3]);
        #pragma unroll
        for (int j = 0; j < 4; j++) acc[i][j] *= scale;
    }
    float* scb = sc + ((size_t)b*2048 + d0)*2048 + e0;
    #pragma unroll
    for (int i = 0; i < 4; i++)
        *(float4*)&scb[(size_t)(ty*4+i)*2048 + tx*4] =
            make_float4(acc[i][0], acc[i][1], acc[i][2], acc[i][3]);
    #pragma unroll
    for (int i = 0; i < 4; i++) {
        float rm = fmaxf(fmaxf(acc[i][0], acc[i][1]), fmaxf(acc[i][2], acc[i][3]));
        #pragma unroll
        for (int off = 8; off > 0; off >>= 1)
            rm = fmaxf(rm, __shfl_xor_sync(0xffffffffu, rm, off, 16));
        float rs = __expf(acc[i][0]-rm) + __expf(acc[i][1]-rm)
                 + __expf(acc[i][2]-rm) + __expf(acc[i][3]-rm);
        #pragma unroll
        for (int off = 8; off > 0; off >>= 1)
            rs += __shfl_xor_sync(0xffffffffu, rs, off, 16);
        if (tx == 0) {
            size_t idx = ((size_t)b*2048 + d0 + ty*4 + i)*32 + blockIdx.x;
            pmax[idx] = rm;
            psum[idx] = rs;
        }
    }
}

// ---- combine per-tile partials into row max and 1/sum (8 rows/block) ---------
__global__ void k_softfinal_v(const float* __restrict__ pmax, const float* __restrict__ psum,
                              float* __restrict__ smax, float* __restrict__ sinv) {
    size_t row = (size_t)blockIdx.x*8 + (threadIdx.x >> 5);
    int t = threadIdx.x & 31;
    float m = pmax[row*32 + t];
    float s = psum[row*32 + t];
    float M = m;
    #pragma unroll
    for (int off = 16; off > 0; off >>= 1)
        M = fmaxf(M, __shfl_xor_sync(0xffffffffu, M, off));
    float S = s * __expf(m - M);
    #pragma unroll
    for (int off = 16; off > 0; off >>= 1)
        S += __shfl_xor_sync(0xffffffffu, S, off);
    if (t == 0) { smax[row] = M; sinv[row] = 1.f / S; }
}

// ---- v_out partial over d-range: part[bz][b][n][e]  (52-pad, LDS.128 pairs) --
__global__ void __launch_bounds__(128) k_vout(const float* __restrict__ v,
                                              const float* __restrict__ sc,
                                              const float* __restrict__ smax,
                                              const float* __restrict__ sinv,
                                              float* __restrict__ part) {
    int b = blockIdx.y, dz = blockIdx.z;
    int e = blockIdx.x*128 + threadIdx.x;
    __shared__ float vst[64*52];      // [dd][n], 52-pad (16B aligned rows)
    __shared__ float sm[64], si[64];
    unsigned long long acc2[26];
    #pragma unroll
    for (int k = 0; k < 26; k++) acc2[k] = 0ULL;
    if (threadIdx.x < 64) {
        vst[threadIdx.x*52 + 49] = 0.f;
        vst[threadIdx.x*52 + 50] = 0.f;
        vst[threadIdx.x*52 + 51] = 0.f;
    }
    const float* vb = v  + (size_t)b*49*2048;
    const float* sb = sc + (size_t)b*2048*2048;
    const float* mb = smax + (size_t)b*2048;
    const float* ib = sinv + (size_t)b*2048;
    int dlo = dz*512, dhi = dlo + 512;
    for (int d0 = dlo; d0 < dhi; d0 += 64) {
        __syncthreads();
        for (int i = threadIdx.x; i < 49*16; i += 128) {
            int n = i >> 4, dd4 = (i & 15) << 2;
            float4 t = *(const float4*)&vb[n*2048 + d0 + dd4];
            vst[(dd4+0)*52 + n] = t.x;
            vst[(dd4+1)*52 + n] = t.y;
            vst[(dd4+2)*52 + n] = t.z;
            vst[(dd4+3)*52 + n] = t.w;
        }
        if (threadIdx.x < 64) {
            sm[threadIdx.x] = mb[d0 + threadIdx.x];
            si[threadIdx.x] = ib[d0 + threadIdx.x];
        }
        __syncthreads();
        #pragma unroll 4
        for (int dd = 0; dd < 64; dd++) {
            float p = __expf(sb[(size_t)(d0+dd)*2048 + e] - sm[dd]) * si[dd];
            unsigned long long pd = pack2(p, p);
            const ulonglong2* vr = (const ulonglong2*)&vst[dd*52];
            #pragma unroll
            for (int k = 0; k < 13; k++) {
                ulonglong2 vv = vr[k];
                FMA2(acc2[2*k],   pd, vv.x, acc2[2*k]);
                FMA2(acc2[2*k+1], pd, vv.y, acc2[2*k+1]);
            }
        }
    }
    float* pb = part + ((size_t)dz*NB + b)*49*2048;
    #pragma unroll
    for (int k = 0; k < 25; k++) {
        float lo, hi;
        unpack2(acc2[k], lo, hi);
        int n = 2*k;
        pb[(size_t)n*2048 + e] = lo;
        if (n + 1 < 49) pb[(size_t)(n+1)*2048 + e] = hi;
    }
}

// ---- combine 4 d-split partials ----------------------------------------------
__global__ void k_vcombine(const float* __restrict__ part, float* __restrict__ out) {
    size_t i = (size_t)blockIdx.x*256 + threadIdx.x;
    const size_t STRIDE = (size_t)NB*49*2048;
    out[i] = (part[i] + part[i + STRIDE]) + (part[i + 2*STRIDE] + part[i + 3*STRIDE]);
}

// =============================================================================
extern "C" void kernel_launch(void* const* d_in, const int* in_sizes, int n_in,
                              void* d_out, int out_size) {
    const float* Vision = (const float*)d_in[0];
    const float* Audio  = (const float*)d_in[1];
    const float* aW1 = (const float*)d_in[2];
    const float* ab1 = (const float*)d_in[3];
    const float* a_g1 = (const float*)d_in[4];
    const float* a_b1 = (const float*)d_in[5];
    const float* aW2 = (const float*)d_in[6];
    const float* ab2 = (const float*)d_in[7];
    const float* vW1 = (const float*)d_in[8];
    const float* vb1 = (const float*)d_in[9];
    const float* v_g1 = (const float*)d_in[10];
    const float* v_b1 = (const float*)d_in[11];
    const float* vW2 = (const float*)d_in[12];
    const float* vb2 = (const float*)d_in[13];
    const float* kaW = (const float*)d_in[14];
    const float* kab = (const float*)d_in[15];
    const float* ka_g = (const float*)d_in[16];
    const float* ka_b = (const float*)d_in[17];
    const float* kvW = (const float*)d_in[18];
    const float* kvb = (const float*)d_in[19];
    const float* kv_g = (const float*)d_in[20];
    const float* kv_b = (const float*)d_in[21];

    float* out_v = (float*)d_out;                         // (16,49,2048)
    float* out_a = (float*)d_out + (size_t)NB*49*2048;    // (16,64,128)

    float *p_v, *p_tv, *p_vq, *p_vk, *p_sc, *p_ta, *p_aq, *p_ak, *p_sca,
          *p_scl, *p_sft, *p_smax, *p_sinv, *p_pmax, *p_psum, *p_part;
    cudaGetSymbolAddress((void**)&p_v,    g_v);
    cudaGetSymbolAddress((void**)&p_tv,   g_tv);
    cudaGetSymbolAddress((void**)&p_vq,   g_vquery);
    cudaGetSymbolAddress((void**)&p_vk,   g_vkeys);
    cudaGetSymbolAddress((void**)&p_sc,   g_scores);
    cudaGetSymbolAddress((void**)&p_ta,   g_ta);
    cudaGetSymbolAddress((void**)&p_aq,   g_aquery);
    cudaGetSymbolAddress((void**)&p_ak,   g_akeys);
    cudaGetSymbolAddress((void**)&p_sca,  g_scores_a);
    cudaGetSymbolAddress((void**)&p_scl,  g_bnscale);
    cudaGetSymbolAddress((void**)&p_sft,  g_bnshift);
    cudaGetSymbolAddress((void**)&p_smax, g_smax);
    cudaGetSymbolAddress((void**)&p_sinv, g_sinv);
    cudaGetSymbolAddress((void**)&p_pmax, g_pmax);
    cudaGetSymbolAddress((void**)&p_psum, g_psum);
    cudaGetSymbolAddress((void**)&p_part, g_vpart);

    // ---- independent producers (audio + vision) ----
    k_transpose<<<dim3(NB, 64), 256>>>(Vision, p_v);
    k_conv<64,128><<<dim3(64, NB), 128>>>(Audio, kaW, kab, p_ak, 64);
    k_rowAT<128,64,4><<<NB*64/4, 256>>>(Audio, aW1, ab1, p_ta);
    k_convv<<<dim3(16, NB), 128>>>(p_v, kvW, kvb, p_vk);
    k_rowAT<2048,49,4><<<NB*49/4, 256>>>(p_v, vW1, vb1, p_tv);

    // ---- single BN-stats sync point (all 4 BNs) ----
    BNCfg c0{p_ta, a_g1, a_b1, p_scl + 0,   p_sft + 0,   64, 64,   0};
    BNCfg c1{p_ak, ka_g, ka_b, p_scl + 64,  p_sft + 64,  64, 128,  64};
    BNCfg c2{p_tv, v_g1, v_b1, p_scl + 128, p_sft + 128, 49, 49,   128};
    BNCfg c3{p_vk, kv_g, kv_b, p_scl + 192, p_sft + 192, 49, 2048, 177};
    k_bnstats4<<<226, 256>>>(c0, c1, c2, c3);

    // ---- consumers ----
    k_rowBt<64,128,64,16><<<dim3(1, NB*64/16), 128>>>(p_ta, aW2, ab2,
                                                      p_scl + 0, p_sft + 0, p_aq);
    k_scores_a<<<dim3(128, NB), 128>>>(p_ak, p_aq, p_scl + 64, p_sft + 64, p_sca);
    k_aout<<<dim3(64, NB), 128>>>(Audio, p_sca, out_a);
    k_rowBt<49,2048,49,16><<<dim3(16, NB*49/16), 128>>>(p_tv, vW2, vb2,
                                                        p_scl + 128, p_sft + 128, p_vq);
    k_logits_v<<<dim3(32, 32, NB), 256>>>(p_vk, p_vq, p_scl + 192, p_sft + 192,
                                          p_sc, p_pmax, p_psum);
    k_softfinal_v<<<NB*2048/8, 256>>>(p_pmax, p_psum, p_smax, p_sinv);
    k_vout<<<dim3(16, NB, 4), 128>>>(p_v, p_sc, p_smax, p_sinv, p_part);
    k_vcombine<<<(NB*49*2048)/256, 256>>>(p_part, out_v);
}